// round 10
// baseline (speedup 1.0000x reference)
#include <cuda_runtime.h>
#include <cuda_fp16.h>
#include <math.h>
#include <stdint.h>

// B=8, S=256, N=256, C=64, NH=8, D=2048
// P (fp16): flat ((b*256+s)*256+n)*256+c ; n:[0,64)=q(norm) [64,128)=k(norm)
// [128,192)=vH [192,256)=vV
__device__ __half g_Ph[134217728];
__device__ __half g_AHm[4194304];   // [bh][s][t]
__device__ __half g_AVm[4194304];
__device__ __half g_Wh[16384];      // qkv_w fp16 [256][64]
__device__ __half g_PWh[4096];      // proj_w fp16 [64][64]

#define DINL __device__ __forceinline__

DINL uint32_t su32(const void* p) { return (uint32_t)__cvta_generic_to_shared(p); }

DINL void ldsm4(uint32_t r[4], const void* p) {
    asm volatile("ldmatrix.sync.aligned.m8n8.x4.shared.b16 {%0,%1,%2,%3},[%4];"
        : "=r"(r[0]), "=r"(r[1]), "=r"(r[2]), "=r"(r[3]) : "r"(su32(p)));
}
DINL void ldsm4t(uint32_t r[4], const void* p) {
    asm volatile("ldmatrix.sync.aligned.m8n8.x4.trans.shared.b16 {%0,%1,%2,%3},[%4];"
        : "=r"(r[0]), "=r"(r[1]), "=r"(r[2]), "=r"(r[3]) : "r"(su32(p)));
}
DINL void mma8(float c[4], const uint32_t a[4], uint32_t b0, uint32_t b1) {
    asm volatile("mma.sync.aligned.m16n8k16.row.col.f32.f16.f16.f32 "
        "{%0,%1,%2,%3},{%4,%5,%6,%7},{%8,%9},{%0,%1,%2,%3};"
        : "+f"(c[0]), "+f"(c[1]), "+f"(c[2]), "+f"(c[3])
        : "r"(a[0]), "r"(a[1]), "r"(a[2]), "r"(a[3]), "r"(b0), "r"(b1));
}
DINL void cpa16(void* s, const void* g) {
    asm volatile("cp.async.cg.shared.global [%0], [%1], 16;" :: "r"(su32(s)), "l"(g));
}
DINL void cpcommit() { asm volatile("cp.async.commit_group;"); }
DINL void cpwait0()  { asm volatile("cp.async.wait_group 0;"); }
DINL void cpwait1()  { asm volatile("cp.async.wait_group 1;"); }

// ---------------------------------------------------------------------------
// Kernel 0: one-time fp32 -> fp16 weight conversion.
// ---------------------------------------------------------------------------
__global__ void k_cvt(const float* __restrict__ qkv_w, const float* __restrict__ proj_w)
{
    int t = blockIdx.x * 256 + threadIdx.x;
    if (t < 16384) g_Wh[t]  = __float2half_rn(qkv_w[t]);
    if (t < 4096)  g_PWh[t] = __float2half_rn(proj_w[t]);
}

// ---------------------------------------------------------------------------
// Kernel 1: P = X @ W^T + bias, fused q/k 8-row-group L2 norm.
// grid(2048,4): x=b*256+s, y=64-row quarter. 256 thr = 8 warps (2x4),
// warp tile 32x64. 2 CTAs/SM.
// ---------------------------------------------------------------------------
__global__ void __launch_bounds__(256, 2)
k_qkv(const float* __restrict__ x, const float* __restrict__ bias_)
{
    extern __shared__ __half sm[];
    __half* Xs = sm;                       // [64][72]  = 4608 h
    __half* Ws = sm + 64 * 72;             // [256][72] = 18432 h
    __half* St = sm;                       // stage reuse: [64][288] = 18432 h
    float*  bsh = (float*)((char*)sm + 46080);  // [256]
    float*  gss = bsh + 256;                    // [8]

    const int bs = blockIdx.x, quarter = blockIdx.y, n0 = quarter << 6;
    const int tid = threadIdx.x, lane = tid & 31, warp = tid >> 5;
    const int wr = warp >> 2, wc = warp & 3;

    { // X tile (64 x 64 fp32) -> fp16 smem
        int row = tid >> 2, k0 = (tid & 3) << 4;
        const float* src = x + ((size_t)bs * 256 + n0 + row) * 64 + k0;
        __half* dst = Xs + row * 72 + k0;
        #pragma unroll
        for (int i = 0; i < 4; i++) {
            float4 v = *(const float4*)(src + i * 4);
            dst[i*4+0] = __float2half_rn(v.x); dst[i*4+1] = __float2half_rn(v.y);
            dst[i*4+2] = __float2half_rn(v.z); dst[i*4+3] = __float2half_rn(v.w);
        }
    }
    { // W fp16 via cp.async: 2048 segs / 256 thr = 8 each
        #pragma unroll
        for (int i = 0; i < 8; i++) {
            int seg = tid * 8 + i;
            int row = seg >> 3, off = (seg & 7) << 3;
            cpa16(Ws + row * 72 + off, g_Wh + row * 64 + off);
        }
        cpcommit();
    }
    bsh[tid] = bias_[tid];
    if (tid < 8) gss[tid] = 0.f;
    cpwait0();
    __syncthreads();

    float acc[2][8][4];
    #pragma unroll
    for (int mt = 0; mt < 2; mt++)
        #pragma unroll
        for (int nt = 0; nt < 8; nt++)
            #pragma unroll
            for (int q = 0; q < 4; q++) acc[mt][nt][q] = 0.f;

    #pragma unroll
    for (int kk = 0; kk < 4; kk++) {
        uint32_t af[2][4];
        #pragma unroll
        for (int mt = 0; mt < 2; mt++)
            ldsm4(af[mt], Xs + (wr*32 + mt*16 + (lane & 15)) * 72
                             + kk*16 + ((lane >> 4) << 3));
        #pragma unroll
        for (int g = 0; g < 4; g++) {
            uint32_t r[4];
            ldsm4(r, Ws + (wc*64 + g*16 + (lane & 15)) * 72
                        + kk*16 + ((lane >> 4) << 3));
            #pragma unroll
            for (int mt = 0; mt < 2; mt++) {
                mma8(acc[mt][2*g],   af[mt], r[0], r[2]);
                mma8(acc[mt][2*g+1], af[mt], r[1], r[3]);
            }
        }
    }

    // bias before norm
    #pragma unroll
    for (int nt = 0; nt < 8; nt++) {
        float b0 = bsh[wc*64 + nt*8 + 2*(lane & 3)];
        float b1 = bsh[wc*64 + nt*8 + 2*(lane & 3) + 1];
        #pragma unroll
        for (int mt = 0; mt < 2; mt++) {
            acc[mt][nt][0] += b0; acc[mt][nt][1] += b1;
            acc[mt][nt][2] += b0; acc[mt][nt][3] += b1;
        }
    }

    // q/k 8-row-group norms (quarters 0,1 only). 8 groups per block.
    if (quarter < 2) {
        #pragma unroll
        for (int mt = 0; mt < 2; mt++) {
            float p01 = 0.f, p23 = 0.f;
            #pragma unroll
            for (int nt = 0; nt < 8; nt++) {
                p01 += acc[mt][nt][0]*acc[mt][nt][0] + acc[mt][nt][1]*acc[mt][nt][1];
                p23 += acc[mt][nt][2]*acc[mt][nt][2] + acc[mt][nt][3]*acc[mt][nt][3];
            }
            #pragma unroll
            for (int off = 16; off > 0; off >>= 1) {
                p01 += __shfl_xor_sync(0xffffffffu, p01, off);
                p23 += __shfl_xor_sync(0xffffffffu, p23, off);
            }
            if (lane == 0) {
                atomicAdd(&gss[wr*4 + mt*2],     p01);
                atomicAdd(&gss[wr*4 + mt*2 + 1], p23);
            }
        }
    }
    __syncthreads();

    // stage scaled fp16 into smem (stride 288, 16B-unit swizzle)
    #pragma unroll
    for (int mt = 0; mt < 2; mt++) {
        float s01 = 1.f, s23 = 1.f;
        if (quarter < 2) {
            s01 = 1.f / fmaxf(sqrtf(gss[wr*4 + mt*2]),     1e-12f);
            s23 = 1.f / fmaxf(sqrtf(gss[wr*4 + mt*2 + 1]), 1e-12f);
        }
        int r0 = wr*32 + mt*16 + (lane >> 2);
        int xr = (r0 >> 1) & 1;
        #pragma unroll
        for (int nt = 0; nt < 8; nt++) {
            int c = wc*64 + nt*8 + 2*(lane & 3);
            int u = c >> 3, sub = c & 7;
            int up = ((u ^ xr) << 3) + sub;
            *(__half2*)(St + r0*288 + up) =
                __floats2half2_rn(acc[mt][nt][0]*s01, acc[mt][nt][1]*s01);
            *(__half2*)(St + (r0+8)*288 + up) =
                __floats2half2_rn(acc[mt][nt][2]*s23, acc[mt][nt][3]*s23);
        }
    }
    __syncthreads();

    { // coalesced global store: 64 rows x 32 segs
        int row = tid >> 2, q = tid & 3;
        int xr = (row >> 1) & 1;
        const __half* base = St + row * 288;
        __half* gp = g_Ph + ((size_t)bs * 256 + n0 + row) * 256;
        #pragma unroll
        for (int i = 0; i < 8; i++) {
            int u = q + 4*i;
            uint4 v = *(const uint4*)(base + ((u ^ xr) << 3));
            *(uint4*)(gp + (u << 3)) = v;
        }
    }
}

// ---------------------------------------------------------------------------
// Kernel 2: sim = Qn @ Kn^T per (b,h) + dual softmax.
// grid(64,4): bh, 64-row s-quarter. 256 thr (2x4 warps), warp 32x64 over
// 64x256. K=2048, chunk 32, 3-stage pipeline, one sync/chunk. 2 CTAs/SM.
// ---------------------------------------------------------------------------
__global__ void __launch_bounds__(256, 2)
k_attn(const float* __restrict__ t1g, const float* __restrict__ t2g)
{
    extern __shared__ __half sm2[];
    __half* Qs = sm2;                          // 3 x [64][40]  = 3*2560
    __half* Ks = sm2 + 3 * 2560;               // 3 x [256][40] = 3*10240
    float*  rs1 = (float*)(Ks + 3 * 10240);    // [64]
    float*  rs2 = rs1 + 64;                    // [64]

    const int bh = blockIdx.x, s0 = blockIdx.y << 6;
    const int b = bh >> 3, h = bh & 7;
    const __half* qb = g_Ph + (size_t)b * 16777216 + h * 2048;
    const __half* kb = qb + 16384;

    const int tid = threadIdx.x, lane = tid & 31, warp = tid >> 5;
    const int wr = warp >> 2, wc = warp & 3;

    if (tid < 64) { rs1[tid] = 0.f; rs2[tid] = 0.f; }

    auto loadQK = [&](int buf, int c) {
        int d0 = c * 32;
        { // Q: 256 segs, 1 per thread
            int row = tid >> 2, off = (tid & 3) << 3;
            cpa16(Qs + buf*2560 + row*40 + off,
                  qb + (size_t)(s0 + row) * 65536 + d0 + off);
        }
        #pragma unroll
        for (int i = 0; i < 4; i++) { // K: 1024 segs, 4 per thread
            int seg = tid * 4 + i, row = seg >> 2, off = (seg & 3) << 3;
            cpa16(Ks + buf*10240 + row*40 + off,
                  kb + (size_t)row * 65536 + d0 + off);
        }
        cpcommit();
    };

    float acc[2][8][4];
    #pragma unroll
    for (int mt = 0; mt < 2; mt++)
        #pragma unroll
        for (int nt = 0; nt < 8; nt++)
            #pragma unroll
            for (int q = 0; q < 4; q++) acc[mt][nt][q] = 0.f;

    loadQK(0, 0);
    loadQK(1, 1);
    for (int c = 0; c < 64; c++) {
        if (c < 63) cpwait1(); else cpwait0();
        __syncthreads();
        if (c + 2 < 64) loadQK((c + 2) % 3, c + 2);
        const int st = c % 3;
        const __half* Q = Qs + st * 2560;
        const __half* K = Ks + st * 10240;
        #pragma unroll
        for (int kk = 0; kk < 2; kk++) {
            uint32_t af[2][4];
            #pragma unroll
            for (int mt = 0; mt < 2; mt++)
                ldsm4(af[mt], Q + (wr*32 + mt*16 + (lane & 15)) * 40
                                + kk*16 + ((lane >> 4) << 3));
            #pragma unroll
            for (int g = 0; g < 4; g++) {
                uint32_t r[4];
                ldsm4(r, K + (wc*64 + g*16 + (lane & 15)) * 40
                           + kk*16 + ((lane >> 4) << 3));
                #pragma unroll
                for (int mt = 0; mt < 2; mt++) {
                    mma8(acc[mt][2*g],   af[mt], r[0], r[2]);
                    mma8(acc[mt][2*g+1], af[mt], r[1], r[3]);
                }
            }
        }
    }
    __syncthreads();

    const float t1 = t1g[h], t2 = t2g[h];

    // pass 1: row sums of exp
    #pragma unroll
    for (int mt = 0; mt < 2; mt++) {
        float p1a = 0.f, p1b = 0.f, p2a = 0.f, p2b = 0.f;
        #pragma unroll
        for (int nt = 0; nt < 8; nt++) {
            p1a += __expf(acc[mt][nt][0]*t1) + __expf(acc[mt][nt][1]*t1);
            p1b += __expf(acc[mt][nt][2]*t1) + __expf(acc[mt][nt][3]*t1);
            p2a += __expf(acc[mt][nt][0]*t2) + __expf(acc[mt][nt][1]*t2);
            p2b += __expf(acc[mt][nt][2]*t2) + __expf(acc[mt][nt][3]*t2);
        }
        #pragma unroll
        for (int off = 1; off < 4; off <<= 1) {
            p1a += __shfl_xor_sync(0xffffffffu, p1a, off);
            p1b += __shfl_xor_sync(0xffffffffu, p1b, off);
            p2a += __shfl_xor_sync(0xffffffffu, p2a, off);
            p2b += __shfl_xor_sync(0xffffffffu, p2b, off);
        }
        if ((lane & 3) == 0) {
            int r0 = wr*32 + mt*16 + (lane >> 2);
            atomicAdd(&rs1[r0], p1a);     atomicAdd(&rs1[r0 + 8], p1b);
            atomicAdd(&rs2[r0], p2a);     atomicAdd(&rs2[r0 + 8], p2b);
        }
    }
    __syncthreads();

    // pass 2: normalize + store fp16
    #pragma unroll
    for (int mt = 0; mt < 2; mt++) {
        int r0 = wr*32 + mt*16 + (lane >> 2);
        float i1a = 1.f / rs1[r0], i1b = 1.f / rs1[r0 + 8];
        float i2a = 1.f / rs2[r0], i2b = 1.f / rs2[r0 + 8];
        #pragma unroll
        for (int nt = 0; nt < 8; nt++) {
            int col = wc*64 + nt*8 + 2*(lane & 3);
            size_t base = (size_t)bh * 65536 + (size_t)(s0 + r0) * 256 + col;
            *(__half2*)(g_AHm + base) = __floats2half2_rn(
                __expf(acc[mt][nt][0]*t1)*i1a, __expf(acc[mt][nt][1]*t1)*i1a);
            *(__half2*)(g_AHm + base + 2048) = __floats2half2_rn(
                __expf(acc[mt][nt][2]*t1)*i1b, __expf(acc[mt][nt][3]*t1)*i1b);
            *(__half2*)(g_AVm + base) = __floats2half2_rn(
                __expf(acc[mt][nt][0]*t2)*i2a, __expf(acc[mt][nt][1]*t2)*i2a);
            *(__half2*)(g_AVm + base + 2048) = __floats2half2_rn(
                __expf(acc[mt][nt][2]*t2)*i2b, __expf(acc[mt][nt][3]*t2)*i2b);
        }
    }
}

// ---------------------------------------------------------------------------
// Kernel 3: xsum = A_H@V_H + A_V@V_Vfinal, 64s x 256d per block, fused proj
// epilogue. grid(64,32): bh; tile: bits[0:1]=s-quarter, bits[2:4]=dg.
// 256 thr (2x4 warps), 2-stage distance-1 prefetch (race-free). 2 CTAs/SM.
// ---------------------------------------------------------------------------
__global__ void __launch_bounds__(256, 2)
k_av(const float* __restrict__ pb, float* __restrict__ out)
{
    extern __shared__ __half sm3[];
    __half* AHs = sm3;                     // 2 x [64][40]  = 2*2560
    __half* AVs = AHs + 2 * 2560;          // 2 x [64][40]
    __half* Vhs = AVs + 2 * 2560;          // 2 x [32][264] = 2*8448
    __half* Vvs = Vhs + 2 * 8448;          // 2 x [32][264]
    __half* PWs = Vvs + 2 * 8448;          // [64][72] = 4608
    float*  pbs = (float*)(PWs + 4608);    // [64]
    __half* XSs = sm3;                     // epilogue reuse: [64][264] = 16896 h

    const int bh = blockIdx.x, b = bh >> 3, h = bh & 7;
    const int tile = blockIdx.y;
    const int s0 = (tile & 3) << 6, dg = tile >> 2;
    const int j0 = dg << 2;

    const int tid = threadIdx.x, lane = tid & 31, warp = tid >> 5;
    const int wr = warp >> 2, wc = warp & 3;

    const __half* AHg = g_AHm + (size_t)bh * 65536 + (size_t)s0 * 256;
    const __half* AVg = g_AVm + (size_t)bh * 65536 + (size_t)s0 * 256;
    const __half* vh  = g_Ph + (size_t)b * 16777216 + 32768 + h * 2048 + dg * 256;
    const __half* vv  = g_Ph + (size_t)b * 16777216 + (size_t)(h*32 + j0) * 65536 + 49152;

    { // proj weight: 512 segs, 2 per thread (rides with first chunk's group)
        #pragma unroll
        for (int i = 0; i < 2; i++) {
            int seg = tid * 2 + i, row = seg >> 3, off = (seg & 7) << 3;
            cpa16(PWs + row * 72 + off, g_PWh + row * 64 + off);
        }
    }
    if (tid < 64) pbs[tid] = pb[tid];

    auto loadAV = [&](int buf, int c) {
        int t0 = c * 32;
        { // A: 256 segs each, 1 per thread
            int row = tid >> 2, off = (tid & 3) << 3;
            cpa16(AHs + buf*2560 + row*40 + off, AHg + (size_t)row * 256 + t0 + off);
            cpa16(AVs + buf*2560 + row*40 + off, AVg + (size_t)row * 256 + t0 + off);
        }
        #pragma unroll
        for (int i = 0; i < 4; i++) { // V: 1024 segs each, 4 per thread
            int sg = tid * 4 + i, row = sg >> 5, off = (sg & 31) << 3;
            cpa16(Vhs + buf*8448 + row*264 + off,
                  vh + (size_t)(t0 + row) * 65536 + off);
            int jj = off >> 6, cc = off & 63;
            cpa16(Vvs + buf*8448 + row*264 + off,
                  vv + (size_t)jj * 65536 + (t0 + row) * 64 + cc);
        }
        cpcommit();
    };

    float acc[2][8][4];
    #pragma unroll
    for (int mt = 0; mt < 2; mt++)
        #pragma unroll
        for (int nt = 0; nt < 8; nt++)
            #pragma unroll
            for (int q = 0; q < 4; q++) acc[mt][nt][q] = 0.f;

    // distance-1 prefetch, 2 stages, race-free:
    // stage s is rewritten (chunk c+2, issued in iter c+1) only after iter c's
    // trailing __syncthreads(), by which point all reads of chunk c are done.
    loadAV(0, 0);
    for (int c = 0; c < 8; c++) {
        if (c + 1 < 8) { loadAV((c + 1) & 1, c + 1); cpwait1(); }
        else cpwait0();
        __syncthreads();
        const int st = c & 1;
        const __half* AH = AHs + st * 2560;
        const __half* AV = AVs + st * 2560;
        const __half* VH = Vhs + st * 8448;
        const __half* VV = Vvs + st * 8448;
        #pragma unroll
        for (int kk = 0; kk < 2; kk++) {
            uint32_t aH[2][4], aV[2][4];
            #pragma unroll
            for (int mt = 0; mt < 2; mt++) {
                ldsm4(aH[mt], AH + (wr*32 + mt*16 + (lane & 15)) * 40
                                 + kk*16 + ((lane >> 4) << 3));
                ldsm4(aV[mt], AV + (wr*32 + mt*16 + (lane & 15)) * 40
                                 + kk*16 + ((lane >> 4) << 3));
            }
            #pragma unroll
            for (int g = 0; g < 4; g++) {
                int D0 = wc*64 + g*16;
                int trow = kk*16 + ((lane >> 4) << 3) + (lane & 7);
                int dcol = D0 + (((lane >> 3) & 1) << 3);
                uint32_t r[4];
                ldsm4t(r, VH + trow*264 + dcol);
                #pragma unroll
                for (int mt = 0; mt < 2; mt++) {
                    mma8(acc[mt][2*g],   aH[mt], r[0], r[2]);
                    mma8(acc[mt][2*g+1], aH[mt], r[1], r[3]);
                }
                ldsm4t(r, VV + trow*264 + dcol);
                #pragma unroll
                for (int mt = 0; mt < 2; mt++) {
                    mma8(acc[mt][2*g],   aV[mt], r[0], r[2]);
                    mma8(acc[mt][2*g+1], aV[mt], r[1], r[3]);
                }
            }
        }
        __syncthreads();
    }

    // stage xsum fp16 -> smem, then proj MMA
    #pragma unroll
    for (int mt = 0; mt < 2; mt++) {
        int r0 = wr*32 + mt*16 + (lane >> 2);
        #pragma unroll
        for (int nt = 0; nt < 8; nt++) {
            int col = wc*64 + nt*8 + 2*(lane & 3);
            *(__half2*)(XSs + r0*264 + col) =
                __floats2half2_rn(acc[mt][nt][0], acc[mt][nt][1]);
            *(__half2*)(XSs + (r0+8)*264 + col) =
                __floats2half2_rn(acc[mt][nt][2], acc[mt][nt][3]);
        }
    }
    __syncthreads();

    float a2[2][8][4];
    #pragma unroll
    for (int mt = 0; mt < 2; mt++)
        #pragma unroll
        for (int nt = 0; nt < 8; nt++)
            #pragma unroll
            for (int q = 0; q < 4; q++) a2[mt][nt][q] = 0.f;

    #pragma unroll
    for (int kk = 0; kk < 4; kk++) {
        uint32_t af[2][4];
        #pragma unroll
        for (int mt = 0; mt < 2; mt++)
            ldsm4(af[mt], XSs + (wr*32 + mt*16 + (lane & 15)) * 264
                              + wc*64 + kk*16 + ((lane >> 4) << 3));
        #pragma unroll
        for (int g = 0; g < 4; g++) {
            uint32_t r[4];
            ldsm4(r, PWs + (g*16 + (lane & 15)) * 72
                         + kk*16 + ((lane >> 4) << 3));
            #pragma unroll
            for (int mt = 0; mt < 2; mt++) {
                mma8(a2[mt][2*g],   af[mt], r[0], r[2]);
                mma8(a2[mt][2*g+1], af[mt], r[1], r[3]);
            }
        }
    }

    #pragma unroll
    for (int mt = 0; mt < 2; mt++) {
        int r0 = wr*32 + mt*16 + (lane >> 2);
        #pragma unroll
        for (int nt = 0; nt < 8; nt++) {
            int co = nt*8 + 2*(lane & 3);
            float b0 = pbs[co], b1 = pbs[co + 1];
            float* o0 = out + ((size_t)(b*256 + s0 + r0) * 256
                               + h*32 + j0 + wc) * 64 + co;
            float* o1 = out + ((size_t)(b*256 + s0 + r0 + 8) * 256
                               + h*32 + j0 + wc) * 64 + co;
            *(float2*)o0 = make_float2(a2[mt][nt][0] + b0, a2[mt][nt][1] + b1);
            *(float2*)o1 = make_float2(a2[mt][nt][2] + b0, a2[mt][nt][3] + b1);
        }
    }
}

// ---------------------------------------------------------------------------
extern "C" void kernel_launch(void* const* d_in, const int* in_sizes, int n_in,
                              void* d_out, int out_size)
{
    const float* x      = (const float*)d_in[0];
    const float* qkv_w  = (const float*)d_in[1];
    const float* qkv_b  = (const float*)d_in[2];
    const float* proj_w = (const float*)d_in[3];
    const float* proj_b = (const float*)d_in[4];
    const float* t1     = (const float*)d_in[5];
    const float* t2     = (const float*)d_in[6];
    float* out = (float*)d_out;

    const int smem1 = 46080 + 256*4 + 32;                        // ~47.1 KB
    const int smem2 = (3*2560 + 3*10240) * 2 + 128 * 4;          // ~77.3 KB
    const int smem3 = (2*2560*2 + 2*8448*2 + 4608) * 2 + 64*4;   // ~97.5 KB

    cudaFuncSetAttribute((const void*)k_qkv,
                         cudaFuncAttributeMaxDynamicSharedMemorySize, smem1);
    cudaFuncSetAttribute((const void*)k_attn,
                         cudaFuncAttributeMaxDynamicSharedMemorySize, smem2);
    cudaFuncSetAttribute((const void*)k_av,
                         cudaFuncAttributeMaxDynamicSharedMemorySize, smem3);

    k_cvt <<<64, 256>>>(qkv_w, proj_w);
    k_qkv <<<dim3(2048, 4), 256, smem1>>>(x, qkv_b);
    k_attn<<<dim3(64, 4),   256, smem2>>>(t1, t2);
    k_av  <<<dim3(64, 32),  256, smem3>>>(proj_b, out);
}

// round 13
// speedup vs baseline: 1.1998x; 1.1998x over previous
#include <cuda_runtime.h>
#include <cuda_fp16.h>
#include <math.h>
#include <stdint.h>

// B=8, S=256, N=256, C=64, NH=8, D=2048
// P (fp16): flat ((b*256+s)*256+n)*256+c ; n:[0,64)=q(norm) [64,128)=k(norm)
// [128,192)=vH [192,256)=vV
__device__ __half g_Ph[134217728];
__device__ __half g_Wh[16384];      // qkv_w fp16 [256][64]
__device__ __half g_PWh[4096];      // proj_w fp16 [64][64]

#define DINL __device__ __forceinline__

DINL uint32_t su32(const void* p) { return (uint32_t)__cvta_generic_to_shared(p); }

DINL void ldsm4(uint32_t r[4], const void* p) {
    asm volatile("ldmatrix.sync.aligned.m8n8.x4.shared.b16 {%0,%1,%2,%3},[%4];"
        : "=r"(r[0]), "=r"(r[1]), "=r"(r[2]), "=r"(r[3]) : "r"(su32(p)));
}
DINL void ldsm4t(uint32_t r[4], const void* p) {
    asm volatile("ldmatrix.sync.aligned.m8n8.x4.trans.shared.b16 {%0,%1,%2,%3},[%4];"
        : "=r"(r[0]), "=r"(r[1]), "=r"(r[2]), "=r"(r[3]) : "r"(su32(p)));
}
DINL void mma8(float c[4], const uint32_t a[4], uint32_t b0, uint32_t b1) {
    asm volatile("mma.sync.aligned.m16n8k16.row.col.f32.f16.f16.f32 "
        "{%0,%1,%2,%3},{%4,%5,%6,%7},{%8,%9},{%0,%1,%2,%3};"
        : "+f"(c[0]), "+f"(c[1]), "+f"(c[2]), "+f"(c[3])
        : "r"(a[0]), "r"(a[1]), "r"(a[2]), "r"(a[3]), "r"(b0), "r"(b1));
}
DINL void cpa16(void* s, const void* g) {
    asm volatile("cp.async.cg.shared.global [%0], [%1], 16;" :: "r"(su32(s)), "l"(g));
}
DINL void cpcommit() { asm volatile("cp.async.commit_group;"); }
DINL void cpwait0()  { asm volatile("cp.async.wait_group 0;"); }
DINL void cpwait1()  { asm volatile("cp.async.wait_group 1;"); }

// ---------------------------------------------------------------------------
// Kernel 0: one-time fp32 -> fp16 weight conversion.
// ---------------------------------------------------------------------------
__global__ void k_cvt(const float* __restrict__ qkv_w, const float* __restrict__ proj_w)
{
    int t = blockIdx.x * 256 + threadIdx.x;
    if (t < 16384) g_Wh[t]  = __float2half_rn(qkv_w[t]);
    if (t < 4096)  g_PWh[t] = __float2half_rn(proj_w[t]);
}

// ---------------------------------------------------------------------------
// Kernel 1: P = X @ W^T + bias, fused q/k 8-row-group L2 norm.   (R6 version)
// grid(2048,2). 512 thr = 16 warps (4x4), warp tile 32x64.
// ---------------------------------------------------------------------------
__global__ void __launch_bounds__(512, 1)
k_qkv(const float* __restrict__ x, const float* __restrict__ bias_)
{
    extern __shared__ __half sm[];
    __half* Xs = sm;                       // [128][72]
    __half* Ws = sm + 128 * 72;            // [256][72]
    __half* St = sm;                       // stage, reuse: [128][288]
    float*  bsh = (float*)((char*)sm + 73728);  // [256]
    float*  gss = bsh + 256;                    // [16]

    const int bs = blockIdx.x, half_ = blockIdx.y, n0 = half_ << 7;
    const int tid = threadIdx.x, lane = tid & 31, warp = tid >> 5;
    const int wr = warp >> 2, wc = warp & 3;

    { // X tile (128 x 64 fp32) -> fp16 smem
        int row = tid >> 2, k0 = (tid & 3) << 4;
        const float* src = x + ((size_t)bs * 256 + n0 + row) * 64 + k0;
        __half* dst = Xs + row * 72 + k0;
        #pragma unroll
        for (int i = 0; i < 4; i++) {
            float4 v = *(const float4*)(src + i * 4);
            dst[i*4+0] = __float2half_rn(v.x); dst[i*4+1] = __float2half_rn(v.y);
            dst[i*4+2] = __float2half_rn(v.z); dst[i*4+3] = __float2half_rn(v.w);
        }
    }
    { // W fp16 via cp.async
        #pragma unroll
        for (int i = 0; i < 4; i++) {
            int seg = tid * 4 + i;
            int row = seg >> 3, off = (seg & 7) << 3;
            cpa16(Ws + row * 72 + off, g_Wh + row * 64 + off);
        }
        cpcommit();
    }
    if (tid < 256) bsh[tid] = bias_[tid];
    if (tid < 16)  gss[tid] = 0.f;
    cpwait0();
    __syncthreads();

    float acc[2][8][4];
    #pragma unroll
    for (int mt = 0; mt < 2; mt++)
        #pragma unroll
        for (int nt = 0; nt < 8; nt++)
            #pragma unroll
            for (int q = 0; q < 4; q++) acc[mt][nt][q] = 0.f;

    #pragma unroll
    for (int kk = 0; kk < 4; kk++) {
        uint32_t af[2][4];
        #pragma unroll
        for (int mt = 0; mt < 2; mt++)
            ldsm4(af[mt], Xs + (wr*32 + mt*16 + (lane & 15)) * 72
                             + kk*16 + ((lane >> 4) << 3));
        #pragma unroll
        for (int g = 0; g < 4; g++) {
            uint32_t r[4];
            ldsm4(r, Ws + (wc*64 + g*16 + (lane & 15)) * 72
                        + kk*16 + ((lane >> 4) << 3));
            #pragma unroll
            for (int mt = 0; mt < 2; mt++) {
                mma8(acc[mt][2*g],   af[mt], r[0], r[2]);
                mma8(acc[mt][2*g+1], af[mt], r[1], r[3]);
            }
        }
    }

    #pragma unroll
    for (int nt = 0; nt < 8; nt++) {
        float b0 = bsh[wc*64 + nt*8 + 2*(lane & 3)];
        float b1 = bsh[wc*64 + nt*8 + 2*(lane & 3) + 1];
        #pragma unroll
        for (int mt = 0; mt < 2; mt++) {
            acc[mt][nt][0] += b0; acc[mt][nt][1] += b1;
            acc[mt][nt][2] += b0; acc[mt][nt][3] += b1;
        }
    }

    if (half_ == 0) {
        #pragma unroll
        for (int mt = 0; mt < 2; mt++) {
            float p01 = 0.f, p23 = 0.f;
            #pragma unroll
            for (int nt = 0; nt < 8; nt++) {
                p01 += acc[mt][nt][0]*acc[mt][nt][0] + acc[mt][nt][1]*acc[mt][nt][1];
                p23 += acc[mt][nt][2]*acc[mt][nt][2] + acc[mt][nt][3]*acc[mt][nt][3];
            }
            #pragma unroll
            for (int off = 16; off > 0; off >>= 1) {
                p01 += __shfl_xor_sync(0xffffffffu, p01, off);
                p23 += __shfl_xor_sync(0xffffffffu, p23, off);
            }
            if (lane == 0) {
                atomicAdd(&gss[wr*4 + mt*2],     p01);
                atomicAdd(&gss[wr*4 + mt*2 + 1], p23);
            }
        }
    }
    __syncthreads();

    #pragma unroll
    for (int mt = 0; mt < 2; mt++) {
        float s01 = 1.f, s23 = 1.f;
        if (half_ == 0) {
            s01 = 1.f / fmaxf(sqrtf(gss[wr*4 + mt*2]),     1e-12f);
            s23 = 1.f / fmaxf(sqrtf(gss[wr*4 + mt*2 + 1]), 1e-12f);
        }
        int r0 = wr*32 + mt*16 + (lane >> 2);
        int xr = (r0 >> 1) & 1;
        #pragma unroll
        for (int nt = 0; nt < 8; nt++) {
            int c = wc*64 + nt*8 + 2*(lane & 3);
            int u = c >> 3, sub = c & 7;
            int up = ((u ^ xr) << 3) + sub;
            *(__half2*)(St + r0*288 + up) =
                __floats2half2_rn(acc[mt][nt][0]*s01, acc[mt][nt][1]*s01);
            *(__half2*)(St + (r0+8)*288 + up) =
                __floats2half2_rn(acc[mt][nt][2]*s23, acc[mt][nt][3]*s23);
        }
    }
    __syncthreads();

    {
        int row = tid >> 2, q = tid & 3;
        int xr = (row >> 1) & 1;
        const __half* base = St + row * 288;
        __half* gp = g_Ph + ((size_t)bs * 256 + n0 + row) * 256;
        #pragma unroll
        for (int i = 0; i < 8; i++) {
            int u = q + 4*i;
            uint4 v = *(const uint4*)(base + ((u ^ xr) << 3));
            *(uint4*)(gp + (u << 3)) = v;
        }
    }
}

// ---------------------------------------------------------------------------
// Kernel 2 (FUSED attn+av): per (b,h,s-half) block, 512 thr = 16 warps (4x4).
// Phase 1: sim = Qn@Kn^T (K=2048, 3-stage pipeline) + dual softmax -> A in
//          SMEM (reuses dead Q/K region).
// Phase 2: dg=0..7: stream V (2-stage, distance-1), AV MMAs with resident A,
//          fused proj epilogue -> out.
//
// SMEM (halves): [0..33792)   phase1 Qs (3x[128][88]) | phase2 AHs [128][264]
//                [33792..101376) phase1 Ks (3x[256][88])
//                               | phase2 AVs [128][264] @33792,
//                                 V stages @67584 (2x8448 VH + 2x8448 VV)
//                                 (XS epilogue stage reuses V region)
//                [101376..105984) PW [64][72]
//                byte 211968: rs1[128], rs2[128], pbs[64] floats
// total 213248 B
// ---------------------------------------------------------------------------
__global__ void __launch_bounds__(512, 1)
k_fused(const float* __restrict__ t1g, const float* __restrict__ t2g,
        const float* __restrict__ pb, float* __restrict__ out)
{
    extern __shared__ __half smf[];
    __half* Qs  = smf;                 // phase 1
    __half* Ks  = smf + 33792;         // phase 1
    __half* AHs = smf;                 // phase 2 [128][264]
    __half* AVs = smf + 33792;         // phase 2 [128][264]
    __half* Vhs = smf + 67584;         // 2 x [32][264]
    __half* Vvs = smf + 84480;         // 2 x [32][264]
    __half* XSs = smf + 67584;         // epilogue stage [128][264]
    __half* PWs = smf + 101376;        // [64][72]
    float*  rs1 = (float*)((char*)smf + 211968);  // [128]
    float*  rs2 = rs1 + 128;                       // [128]
    float*  pbs = rs2 + 128;                       // [64]

    const int bh = blockIdx.x, s0 = blockIdx.y << 7;
    const int b = bh >> 3, h = bh & 7;
    const __half* qb = g_Ph + (size_t)b * 16777216 + h * 2048;
    const __half* kb = qb + 16384;
    const __half* vh = g_Ph + (size_t)b * 16777216 + 32768 + h * 2048;
    const __half* vv = g_Ph + (size_t)b * 16777216 + (size_t)(h*32) * 65536 + 49152;

    const int tid = threadIdx.x, lane = tid & 31, warp = tid >> 5;
    const int wr = warp >> 2, wc = warp & 3;

    if (tid < 128) { rs1[tid] = 0.f; rs2[tid] = 0.f; }
    if (tid < 64)  pbs[tid] = pb[tid];

    // ---------------- phase 1: sim + softmax -> A in smem ----------------
    auto loadQK = [&](int buf, int c) {
        int d0 = c * 64;
        #pragma unroll
        for (int i = 0; i < 2; i++) {
            int seg = tid * 2 + i, row = seg >> 3, off = (seg & 7) << 3;
            cpa16(Qs + buf*11264 + row*88 + off,
                  qb + (size_t)(s0 + row) * 65536 + d0 + off);
        }
        #pragma unroll
        for (int i = 0; i < 4; i++) {
            int seg = tid * 4 + i, row = seg >> 3, off = (seg & 7) << 3;
            cpa16(Ks + buf*22528 + row*88 + off,
                  kb + (size_t)row * 65536 + d0 + off);
        }
        cpcommit();
    };

    float acc[2][8][4];
    #pragma unroll
    for (int mt = 0; mt < 2; mt++)
        #pragma unroll
        for (int nt = 0; nt < 8; nt++)
            #pragma unroll
            for (int q = 0; q < 4; q++) acc[mt][nt][q] = 0.f;

    loadQK(0, 0);
    loadQK(1, 1);
    for (int c = 0; c < 32; c++) {
        if (c < 31) cpwait1(); else cpwait0();
        __syncthreads();
        if (c + 2 < 32) loadQK((c + 2) % 3, c + 2);
        const int st = c % 3;
        const __half* Q = Qs + st * 11264;
        const __half* K = Ks + st * 22528;
        #pragma unroll
        for (int kk = 0; kk < 4; kk++) {
            uint32_t af[2][4];
            #pragma unroll
            for (int mt = 0; mt < 2; mt++)
                ldsm4(af[mt], Q + (wr*32 + mt*16 + (lane & 15)) * 88
                                + kk*16 + ((lane >> 4) << 3));
            #pragma unroll
            for (int g = 0; g < 4; g++) {
                uint32_t r[4];
                ldsm4(r, K + (wc*64 + g*16 + (lane & 15)) * 88
                           + kk*16 + ((lane >> 4) << 3));
                #pragma unroll
                for (int mt = 0; mt < 2; mt++) {
                    mma8(acc[mt][2*g],   af[mt], r[0], r[2]);
                    mma8(acc[mt][2*g+1], af[mt], r[1], r[3]);
                }
            }
        }
    }
    __syncthreads();   // Q/K region dead from here

    const float t1 = t1g[h], t2 = t2g[h];

    // row sums of exp (|sim| <= 1, no max-shift needed)
    #pragma unroll
    for (int mt = 0; mt < 2; mt++) {
        float p1a = 0.f, p1b = 0.f, p2a = 0.f, p2b = 0.f;
        #pragma unroll
        for (int nt = 0; nt < 8; nt++) {
            p1a += __expf(acc[mt][nt][0]*t1) + __expf(acc[mt][nt][1]*t1);
            p1b += __expf(acc[mt][nt][2]*t1) + __expf(acc[mt][nt][3]*t1);
            p2a += __expf(acc[mt][nt][0]*t2) + __expf(acc[mt][nt][1]*t2);
            p2b += __expf(acc[mt][nt][2]*t2) + __expf(acc[mt][nt][3]*t2);
        }
        #pragma unroll
        for (int off = 1; off < 4; off <<= 1) {
            p1a += __shfl_xor_sync(0xffffffffu, p1a, off);
            p1b += __shfl_xor_sync(0xffffffffu, p1b, off);
            p2a += __shfl_xor_sync(0xffffffffu, p2a, off);
            p2b += __shfl_xor_sync(0xffffffffu, p2b, off);
        }
        if ((lane & 3) == 0) {
            int r0 = wr*32 + mt*16 + (lane >> 2);
            atomicAdd(&rs1[r0], p1a);     atomicAdd(&rs1[r0 + 8], p1b);
            atomicAdd(&rs2[r0], p2a);     atomicAdd(&rs2[r0 + 8], p2b);
        }
    }
    __syncthreads();

    // normalize + store A to smem [s][t] stride 264
    #pragma unroll
    for (int mt = 0; mt < 2; mt++) {
        int r0 = wr*32 + mt*16 + (lane >> 2);
        float i1a = 1.f / rs1[r0], i1b = 1.f / rs1[r0 + 8];
        float i2a = 1.f / rs2[r0], i2b = 1.f / rs2[r0 + 8];
        #pragma unroll
        for (int nt = 0; nt < 8; nt++) {
            int col = wc*64 + nt*8 + 2*(lane & 3);
            *(__half2*)(AHs + r0*264 + col) = __floats2half2_rn(
                __expf(acc[mt][nt][0]*t1)*i1a, __expf(acc[mt][nt][1]*t1)*i1a);
            *(__half2*)(AHs + (r0+8)*264 + col) = __floats2half2_rn(
                __expf(acc[mt][nt][2]*t1)*i1b, __expf(acc[mt][nt][3]*t1)*i1b);
            *(__half2*)(AVs + r0*264 + col) = __floats2half2_rn(
                __expf(acc[mt][nt][0]*t2)*i2a, __expf(acc[mt][nt][1]*t2)*i2a);
            *(__half2*)(AVs + (r0+8)*264 + col) = __floats2half2_rn(
                __expf(acc[mt][nt][2]*t2)*i2b, __expf(acc[mt][nt][3]*t2)*i2b);
        }
    }
    // load PW (own cp.async group)
    {
        int row = tid >> 3, off = (tid & 7) << 3;
        cpa16(PWs + row * 72 + off, g_PWh + row * 64 + off);
        cpcommit();
    }
    cpwait0();
    __syncthreads();

    // ---------------- phase 2: dg loop, AV + proj ----------------
    auto loadV = [&](int buf, int dg, int c) {
        int t0 = c * 32;
        #pragma unroll
        for (int i = 0; i < 2; i++) {
            int sg = tid * 2 + i, row = sg >> 5, off = (sg & 31) << 3;
            cpa16(Vhs + buf*8448 + row*264 + off,
                  vh + (size_t)(t0 + row) * 65536 + dg * 256 + off);
            int jj = off >> 6, cc = off & 63;
            cpa16(Vvs + buf*8448 + row*264 + off,
                  vv + (size_t)(dg*4 + jj) * 65536 + (t0 + row) * 64 + cc);
        }
        cpcommit();
    };

    for (int dg = 0; dg < 8; dg++) {
        const int j0 = dg << 2;
        float a1[2][8][4];
        #pragma unroll
        for (int mt = 0; mt < 2; mt++)
            #pragma unroll
            for (int nt = 0; nt < 8; nt++)
                #pragma unroll
                for (int q = 0; q < 4; q++) a1[mt][nt][q] = 0.f;

        loadV(0, dg, 0);
        for (int c = 0; c < 8; c++) {
            if (c + 1 < 8) { loadV((c + 1) & 1, dg, c + 1); cpwait1(); }
            else cpwait0();
            __syncthreads();
            const int st = c & 1, t0 = c * 32;
            const __half* VH = Vhs + st * 8448;
            const __half* VV = Vvs + st * 8448;
            #pragma unroll
            for (int kk = 0; kk < 2; kk++) {
                uint32_t aH[2][4], aV[2][4];
                #pragma unroll
                for (int mt = 0; mt < 2; mt++) {
                    ldsm4(aH[mt], AHs + (wr*32 + mt*16 + (lane & 15)) * 264
                                      + t0 + kk*16 + ((lane >> 4) << 3));
                    ldsm4(aV[mt], AVs + (wr*32 + mt*16 + (lane & 15)) * 264
                                      + t0 + kk*16 + ((lane >> 4) << 3));
                }
                #pragma unroll
                for (int g = 0; g < 4; g++) {
                    int D0 = wc*64 + g*16;
                    int trow = kk*16 + ((lane >> 4) << 3) + (lane & 7);
                    int dcol = D0 + (((lane >> 3) & 1) << 3);
                    uint32_t r[4];
                    ldsm4t(r, VH + trow*264 + dcol);
                    #pragma unroll
                    for (int mt = 0; mt < 2; mt++) {
                        mma8(a1[mt][2*g],   aH[mt], r[0], r[2]);
                        mma8(a1[mt][2*g+1], aH[mt], r[1], r[3]);
                    }
                    ldsm4t(r, VV + trow*264 + dcol);
                    #pragma unroll
                    for (int mt = 0; mt < 2; mt++) {
                        mma8(a1[mt][2*g],   aV[mt], r[0], r[2]);
                        mma8(a1[mt][2*g+1], aV[mt], r[1], r[3]);
                    }
                }
            }
            __syncthreads();
        }

        // stage xsum fp16 into V region (all V reads of this dg are done)
        #pragma unroll
        for (int mt = 0; mt < 2; mt++) {
            int r0 = wr*32 + mt*16 + (lane >> 2);
            #pragma unroll
            for (int nt = 0; nt < 8; nt++) {
                int col = wc*64 + nt*8 + 2*(lane & 3);
                *(__half2*)(XSs + r0*264 + col) =
                    __floats2half2_rn(a1[mt][nt][0], a1[mt][nt][1]);
                *(__half2*)(XSs + (r0+8)*264 + col) =
                    __floats2half2_rn(a1[mt][nt][2], a1[mt][nt][3]);
            }
        }
        __syncthreads();

        float a2[2][8][4];
        #pragma unroll
        for (int mt = 0; mt < 2; mt++)
            #pragma unroll
            for (int nt = 0; nt < 8; nt++)
                #pragma unroll
                for (int q = 0; q < 4; q++) a2[mt][nt][q] = 0.f;

        #pragma unroll
        for (int kk = 0; kk < 4; kk++) {
            uint32_t af[2][4];
            #pragma unroll
            for (int mt = 0; mt < 2; mt++)
                ldsm4(af[mt], XSs + (wr*32 + mt*16 + (lane & 15)) * 264
                                  + wc*64 + kk*16 + ((lane >> 4) << 3));
            #pragma unroll
            for (int g = 0; g < 4; g++) {
                uint32_t r[4];
                ldsm4(r, PWs + (g*16 + (lane & 15)) * 72
                             + kk*16 + ((lane >> 4) << 3));
                #pragma unroll
                for (int mt = 0; mt < 2; mt++) {
                    mma8(a2[mt][2*g],   af[mt], r[0], r[2]);
                    mma8(a2[mt][2*g+1], af[mt], r[1], r[3]);
                }
            }
        }

        #pragma unroll
        for (int mt = 0; mt < 2; mt++) {
            int r0 = wr*32 + mt*16 + (lane >> 2);
            #pragma unroll
            for (int nt = 0; nt < 8; nt++) {
                int co = nt*8 + 2*(lane & 3);
                float b0 = pbs[co], b1 = pbs[co + 1];
                float* o0 = out + ((size_t)(b*256 + s0 + r0) * 256
                                   + h*32 + j0 + wc) * 64 + co;
                float* o1 = out + ((size_t)(b*256 + s0 + r0 + 8) * 256
                                   + h*32 + j0 + wc) * 64 + co;
                *(float2*)o0 = make_float2(a2[mt][nt][0] + b0, a2[mt][nt][1] + b1);
                *(float2*)o1 = make_float2(a2[mt][nt][2] + b0, a2[mt][nt][3] + b1);
            }
        }
        __syncthreads();   // XS region freed before next dg's V loads
    }
}

// ---------------------------------------------------------------------------
extern "C" void kernel_launch(void* const* d_in, const int* in_sizes, int n_in,
                              void* d_out, int out_size)
{
    const float* x      = (const float*)d_in[0];
    const float* qkv_w  = (const float*)d_in[1];
    const float* qkv_b  = (const float*)d_in[2];
    const float* proj_w = (const float*)d_in[3];
    const float* proj_b = (const float*)d_in[4];
    const float* t1     = (const float*)d_in[5];
    const float* t2     = (const float*)d_in[6];
    float* out = (float*)d_out;

    const int smem1 = 73728 + 256*4 + 64;   // ~74.8 KB
    const int smemF = 213248;               // ~208.3 KB

    cudaFuncSetAttribute((const void*)k_qkv,
                         cudaFuncAttributeMaxDynamicSharedMemorySize, smem1);
    cudaFuncSetAttribute((const void*)k_fused,
                         cudaFuncAttributeMaxDynamicSharedMemorySize, smemF);

    k_cvt  <<<64, 256>>>(qkv_w, proj_w);
    k_qkv  <<<dim3(2048, 2), 512, smem1>>>(x, qkv_b);
    k_fused<<<dim3(64, 2),   512, smemF>>>(t1, t2, proj_b, out);
}

// round 16
// speedup vs baseline: 1.3101x; 1.0919x over previous
#include <cuda_runtime.h>
#include <cuda_fp16.h>
#include <math.h>
#include <stdint.h>

// B=8, S=256, N=256, C=64, NH=8, D=2048
// P (fp16): flat ((b*256+s)*256+n)*256+c ; n:[0,64)=q(norm) [64,128)=k(norm)
// [128,192)=vH [192,256)=vV
__device__ __half g_Ph[134217728];
__device__ __half g_Wh[16384];      // qkv_w fp16 [256][64]
__device__ __half g_PWh[4096];      // proj_w fp16 [64][64]

#define DINL __device__ __forceinline__

DINL uint32_t su32(const void* p) { return (uint32_t)__cvta_generic_to_shared(p); }

DINL void ldsm4(uint32_t r[4], const void* p) {
    asm volatile("ldmatrix.sync.aligned.m8n8.x4.shared.b16 {%0,%1,%2,%3},[%4];"
        : "=r"(r[0]), "=r"(r[1]), "=r"(r[2]), "=r"(r[3]) : "r"(su32(p)));
}
DINL void ldsm4t(uint32_t r[4], const void* p) {
    asm volatile("ldmatrix.sync.aligned.m8n8.x4.trans.shared.b16 {%0,%1,%2,%3},[%4];"
        : "=r"(r[0]), "=r"(r[1]), "=r"(r[2]), "=r"(r[3]) : "r"(su32(p)));
}
DINL void mma8(float c[4], const uint32_t a[4], uint32_t b0, uint32_t b1) {
    asm volatile("mma.sync.aligned.m16n8k16.row.col.f32.f16.f16.f32 "
        "{%0,%1,%2,%3},{%4,%5,%6,%7},{%8,%9},{%0,%1,%2,%3};"
        : "+f"(c[0]), "+f"(c[1]), "+f"(c[2]), "+f"(c[3])
        : "r"(a[0]), "r"(a[1]), "r"(a[2]), "r"(a[3]), "r"(b0), "r"(b1));
}
DINL void cpa16(void* s, const void* g) {
    asm volatile("cp.async.cg.shared.global [%0], [%1], 16;" :: "r"(su32(s)), "l"(g));
}
DINL void cpcommit() { asm volatile("cp.async.commit_group;"); }
DINL void cpwait0()  { asm volatile("cp.async.wait_group 0;"); }
DINL void cpwait1()  { asm volatile("cp.async.wait_group 1;"); }

// ---------------------------------------------------------------------------
// Kernel 0: one-time fp32 -> fp16 weight conversion.
// ---------------------------------------------------------------------------
__global__ void k_cvt(const float* __restrict__ qkv_w, const float* __restrict__ proj_w)
{
    int t = blockIdx.x * 256 + threadIdx.x;
    if (t < 16384) g_Wh[t]  = __float2half_rn(qkv_w[t]);
    if (t < 4096)  g_PWh[t] = __float2half_rn(proj_w[t]);
}

// ---------------------------------------------------------------------------
// Kernel 1 (pipelined): P = X @ W^T + bias, fused q/k 8-row-group L2 norm.
// grid(512,2): blockIdx.x = bs-group of 4, y = 128-row half. 512 thr,
// 16 warps (4x4), warp tile 32x64. Per block: W loaded once; 4 tiles
// software-pipelined (X(t+1) LDG prefetch covers tile t compute; STG of
// tile t overlaps tile t+1 MMA). gss double-buffered.
//
// SMEM (halves): Xs 2x[128][72] @0, Ws [256][72] @18432, St [128][288] @36864
//                floats @ half-ofs 73728: bsh[256], gss[2][16]
// total = 73728*2 + 1024 + 128 = 148,608 B
// ---------------------------------------------------------------------------
__global__ void __launch_bounds__(512, 1)
k_qkv(const float* __restrict__ x, const float* __restrict__ bias_)
{
    extern __shared__ __half sm[];
    __half* Xs = sm;               // 2 x [128][72]
    __half* Ws = sm + 18432;       // [256][72]
    __half* St = sm + 36864;       // [128][288]
    float*  bsh = (float*)(sm + 73728);   // [256]
    float*  gss = bsh + 256;              // [2][16]

    const int grp = blockIdx.x, half_ = blockIdx.y, n0 = half_ << 7;
    const int tid = threadIdx.x, lane = tid & 31, warp = tid >> 5;
    const int wr = warp >> 2, wc = warp & 3;
    const int xrow = tid >> 2, xk0 = (tid & 3) << 4;

    { // W fp16 via cp.async (once per block)
        #pragma unroll
        for (int i = 0; i < 4; i++) {
            int seg = tid * 4 + i;
            int row = seg >> 3, off = (seg & 7) << 3;
            cpa16(Ws + row * 72 + off, g_Wh + row * 64 + off);
        }
        cpcommit();
    }
    if (tid < 256) bsh[tid] = bias_[tid];
    if (tid < 32)  gss[tid] = 0.f;

    // prefetch + convert X(0)
    float4 rx[4];
    {
        const float* src = x + ((size_t)(grp * 4) * 256 + n0 + xrow) * 64 + xk0;
        #pragma unroll
        for (int i = 0; i < 4; i++) rx[i] = *(const float4*)(src + i * 4);
        __half* dst = Xs + xrow * 72 + xk0;
        #pragma unroll
        for (int i = 0; i < 4; i++) {
            dst[i*4+0] = __float2half_rn(rx[i].x); dst[i*4+1] = __float2half_rn(rx[i].y);
            dst[i*4+2] = __float2half_rn(rx[i].z); dst[i*4+3] = __float2half_rn(rx[i].w);
        }
    }
    cpwait0();
    __syncthreads();

    for (int t = 0; t < 4; t++) {
        const int bs = grp * 4 + t;
        const __half* Xc  = Xs + (t & 1) * 9216;
        float*        gsc = gss + (t & 1) * 16;

        // prefetch X(t+1) into regs — covered by this tile's compute
        if (t < 3) {
            const float* src = x + ((size_t)(bs + 1) * 256 + n0 + xrow) * 64 + xk0;
            #pragma unroll
            for (int i = 0; i < 4; i++) rx[i] = *(const float4*)(src + i * 4);
        }

        float acc[2][8][4];
        #pragma unroll
        for (int mt = 0; mt < 2; mt++)
            #pragma unroll
            for (int nt = 0; nt < 8; nt++)
                #pragma unroll
                for (int q = 0; q < 4; q++) acc[mt][nt][q] = 0.f;

        #pragma unroll
        for (int kk = 0; kk < 4; kk++) {
            uint32_t af[2][4];
            #pragma unroll
            for (int mt = 0; mt < 2; mt++)
                ldsm4(af[mt], Xc + (wr*32 + mt*16 + (lane & 15)) * 72
                                 + kk*16 + ((lane >> 4) << 3));
            #pragma unroll
            for (int g = 0; g < 4; g++) {
                uint32_t r[4];
                ldsm4(r, Ws + (wc*64 + g*16 + (lane & 15)) * 72
                            + kk*16 + ((lane >> 4) << 3));
                #pragma unroll
                for (int mt = 0; mt < 2; mt++) {
                    mma8(acc[mt][2*g],   af[mt], r[0], r[2]);
                    mma8(acc[mt][2*g+1], af[mt], r[1], r[3]);
                }
            }
        }

        // bias before norm
        #pragma unroll
        for (int nt = 0; nt < 8; nt++) {
            float b0 = bsh[wc*64 + nt*8 + 2*(lane & 3)];
            float b1 = bsh[wc*64 + nt*8 + 2*(lane & 3) + 1];
            #pragma unroll
            for (int mt = 0; mt < 2; mt++) {
                acc[mt][nt][0] += b0; acc[mt][nt][1] += b1;
                acc[mt][nt][2] += b0; acc[mt][nt][3] += b1;
            }
        }

        // q/k 8-row-group norms (half 0 only)
        if (half_ == 0) {
            #pragma unroll
            for (int mt = 0; mt < 2; mt++) {
                float p01 = 0.f, p23 = 0.f;
                #pragma unroll
                for (int nt = 0; nt < 8; nt++) {
                    p01 += acc[mt][nt][0]*acc[mt][nt][0] + acc[mt][nt][1]*acc[mt][nt][1];
                    p23 += acc[mt][nt][2]*acc[mt][nt][2] + acc[mt][nt][3]*acc[mt][nt][3];
                }
                #pragma unroll
                for (int off = 16; off > 0; off >>= 1) {
                    p01 += __shfl_xor_sync(0xffffffffu, p01, off);
                    p23 += __shfl_xor_sync(0xffffffffu, p23, off);
                }
                if (lane == 0) {
                    atomicAdd(&gsc[wr*4 + mt*2],     p01);
                    atomicAdd(&gsc[wr*4 + mt*2 + 1], p23);
                }
            }
        }
        __syncthreads();

        // zero the OTHER gss buffer for tile t+1 (no one reads it now)
        if (tid < 16) gss[((t + 1) & 1) * 16 + tid] = 0.f;

        // stage scaled fp16 into St (stride 288, 16B-unit swizzle)
        #pragma unroll
        for (int mt = 0; mt < 2; mt++) {
            float s01 = 1.f, s23 = 1.f;
            if (half_ == 0) {
                s01 = 1.f / fmaxf(sqrtf(gsc[wr*4 + mt*2]),     1e-12f);
                s23 = 1.f / fmaxf(sqrtf(gsc[wr*4 + mt*2 + 1]), 1e-12f);
            }
            int r0 = wr*32 + mt*16 + (lane >> 2);
            int xr = (r0 >> 1) & 1;
            #pragma unroll
            for (int nt = 0; nt < 8; nt++) {
                int c = wc*64 + nt*8 + 2*(lane & 3);
                int u = c >> 3, sub = c & 7;
                int up = ((u ^ xr) << 3) + sub;
                *(__half2*)(St + r0*288 + up) =
                    __floats2half2_rn(acc[mt][nt][0]*s01, acc[mt][nt][1]*s01);
                *(__half2*)(St + (r0+8)*288 + up) =
                    __floats2half2_rn(acc[mt][nt][2]*s23, acc[mt][nt][3]*s23);
            }
        }
        __syncthreads();

        { // coalesced global store (STG retires into next tile's compute)
            int row = tid >> 2, q = tid & 3;
            int xr = (row >> 1) & 1;
            const __half* base = St + row * 288;
            __half* gp = g_Ph + ((size_t)bs * 256 + n0 + row) * 256;
            #pragma unroll
            for (int i = 0; i < 8; i++) {
                int u = q + 4*i;
                uint4 v = *(const uint4*)(base + ((u ^ xr) << 3));
                *(uint4*)(gp + (u << 3)) = v;
            }
        }

        // convert prefetched X(t+1) into the other Xs buffer
        if (t < 3) {
            __half* dst = Xs + ((t + 1) & 1) * 9216 + xrow * 72 + xk0;
            #pragma unroll
            for (int i = 0; i < 4; i++) {
                dst[i*4+0] = __float2half_rn(rx[i].x); dst[i*4+1] = __float2half_rn(rx[i].y);
                dst[i*4+2] = __float2half_rn(rx[i].z); dst[i*4+3] = __float2half_rn(rx[i].w);
            }
        }
        __syncthreads();
    }
}

// ---------------------------------------------------------------------------
// Kernel 2 (FUSED attn+av): per (b,h,s-half) block, 512 thr = 16 warps (4x4).
// Phase 1: sim = Qn@Kn^T (K=2048, 3-stage pipeline) + dual softmax -> A in
//          SMEM. Phase 2: dg=0..7 stream V (2-stage, distance-1), AV MMAs
//          with resident A, fused proj epilogue -> out.     (R13 version)
// ---------------------------------------------------------------------------
__global__ void __launch_bounds__(512, 1)
k_fused(const float* __restrict__ t1g, const float* __restrict__ t2g,
        const float* __restrict__ pb, float* __restrict__ out)
{
    extern __shared__ __half smf[];
    __half* Qs  = smf;                 // phase 1
    __half* Ks  = smf + 33792;         // phase 1
    __half* AHs = smf;                 // phase 2 [128][264]
    __half* AVs = smf + 33792;         // phase 2 [128][264]
    __half* Vhs = smf + 67584;         // 2 x [32][264]
    __half* Vvs = smf + 84480;         // 2 x [32][264]
    __half* XSs = smf + 67584;         // epilogue stage [128][264]
    __half* PWs = smf + 101376;        // [64][72]
    float*  rs1 = (float*)((char*)smf + 211968);  // [128]
    float*  rs2 = rs1 + 128;                       // [128]
    float*  pbs = rs2 + 128;                       // [64]

    const int bh = blockIdx.x, s0 = blockIdx.y << 7;
    const int b = bh >> 3, h = bh & 7;
    const __half* qb = g_Ph + (size_t)b * 16777216 + h * 2048;
    const __half* kb = qb + 16384;
    const __half* vh = g_Ph + (size_t)b * 16777216 + 32768 + h * 2048;
    const __half* vv = g_Ph + (size_t)b * 16777216 + (size_t)(h*32) * 65536 + 49152;

    const int tid = threadIdx.x, lane = tid & 31, warp = tid >> 5;
    const int wr = warp >> 2, wc = warp & 3;

    if (tid < 128) { rs1[tid] = 0.f; rs2[tid] = 0.f; }
    if (tid < 64)  pbs[tid] = pb[tid];

    auto loadQK = [&](int buf, int c) {
        int d0 = c * 64;
        #pragma unroll
        for (int i = 0; i < 2; i++) {
            int seg = tid * 2 + i, row = seg >> 3, off = (seg & 7) << 3;
            cpa16(Qs + buf*11264 + row*88 + off,
                  qb + (size_t)(s0 + row) * 65536 + d0 + off);
        }
        #pragma unroll
        for (int i = 0; i < 4; i++) {
            int seg = tid * 4 + i, row = seg >> 3, off = (seg & 7) << 3;
            cpa16(Ks + buf*22528 + row*88 + off,
                  kb + (size_t)row * 65536 + d0 + off);
        }
        cpcommit();
    };

    float acc[2][8][4];
    #pragma unroll
    for (int mt = 0; mt < 2; mt++)
        #pragma unroll
        for (int nt = 0; nt < 8; nt++)
            #pragma unroll
            for (int q = 0; q < 4; q++) acc[mt][nt][q] = 0.f;

    loadQK(0, 0);
    loadQK(1, 1);
    for (int c = 0; c < 32; c++) {
        if (c < 31) cpwait1(); else cpwait0();
        __syncthreads();
        if (c + 2 < 32) loadQK((c + 2) % 3, c + 2);
        const int st = c % 3;
        const __half* Q = Qs + st * 11264;
        const __half* K = Ks + st * 22528;
        #pragma unroll
        for (int kk = 0; kk < 4; kk++) {
            uint32_t af[2][4];
            #pragma unroll
            for (int mt = 0; mt < 2; mt++)
                ldsm4(af[mt], Q + (wr*32 + mt*16 + (lane & 15)) * 88
                                + kk*16 + ((lane >> 4) << 3));
            #pragma unroll
            for (int g = 0; g < 4; g++) {
                uint32_t r[4];
                ldsm4(r, K + (wc*64 + g*16 + (lane & 15)) * 88
                           + kk*16 + ((lane >> 4) << 3));
                #pragma unroll
                for (int mt = 0; mt < 2; mt++) {
                    mma8(acc[mt][2*g],   af[mt], r[0], r[2]);
                    mma8(acc[mt][2*g+1], af[mt], r[1], r[3]);
                }
            }
        }
    }
    __syncthreads();   // Q/K region dead from here

    const float t1 = t1g[h], t2 = t2g[h];

    #pragma unroll
    for (int mt = 0; mt < 2; mt++) {
        float p1a = 0.f, p1b = 0.f, p2a = 0.f, p2b = 0.f;
        #pragma unroll
        for (int nt = 0; nt < 8; nt++) {
            p1a += __expf(acc[mt][nt][0]*t1) + __expf(acc[mt][nt][1]*t1);
            p1b += __expf(acc[mt][nt][2]*t1) + __expf(acc[mt][nt][3]*t1);
            p2a += __expf(acc[mt][nt][0]*t2) + __expf(acc[mt][nt][1]*t2);
            p2b += __expf(acc[mt][nt][2]*t2) + __expf(acc[mt][nt][3]*t2);
        }
        #pragma unroll
        for (int off = 1; off < 4; off <<= 1) {
            p1a += __shfl_xor_sync(0xffffffffu, p1a, off);
            p1b += __shfl_xor_sync(0xffffffffu, p1b, off);
            p2a += __shfl_xor_sync(0xffffffffu, p2a, off);
            p2b += __shfl_xor_sync(0xffffffffu, p2b, off);
        }
        if ((lane & 3) == 0) {
            int r0 = wr*32 + mt*16 + (lane >> 2);
            atomicAdd(&rs1[r0], p1a);     atomicAdd(&rs1[r0 + 8], p1b);
            atomicAdd(&rs2[r0], p2a);     atomicAdd(&rs2[r0 + 8], p2b);
        }
    }
    __syncthreads();

    #pragma unroll
    for (int mt = 0; mt < 2; mt++) {
        int r0 = wr*32 + mt*16 + (lane >> 2);
        float i1a = 1.f / rs1[r0], i1b = 1.f / rs1[r0 + 8];
        float i2a = 1.f / rs2[r0], i2b = 1.f / rs2[r0 + 8];
        #pragma unroll
        for (int nt = 0; nt < 8; nt++) {
            int col = wc*64 + nt*8 + 2*(lane & 3);
            *(__half2*)(AHs + r0*264 + col) = __floats2half2_rn(
                __expf(acc[mt][nt][0]*t1)*i1a, __expf(acc[mt][nt][1]*t1)*i1a);
            *(__half2*)(AHs + (r0+8)*264 + col) = __floats2half2_rn(
                __expf(acc[mt][nt][2]*t1)*i1b, __expf(acc[mt][nt][3]*t1)*i1b);
            *(__half2*)(AVs + r0*264 + col) = __floats2half2_rn(
                __expf(acc[mt][nt][0]*t2)*i2a, __expf(acc[mt][nt][1]*t2)*i2a);
            *(__half2*)(AVs + (r0+8)*264 + col) = __floats2half2_rn(
                __expf(acc[mt][nt][2]*t2)*i2b, __expf(acc[mt][nt][3]*t2)*i2b);
        }
    }
    {
        int row = tid >> 3, off = (tid & 7) << 3;
        cpa16(PWs + row * 72 + off, g_PWh + row * 64 + off);
        cpcommit();
    }
    cpwait0();
    __syncthreads();

    auto loadV = [&](int buf, int dg, int c) {
        int t0 = c * 32;
        #pragma unroll
        for (int i = 0; i < 2; i++) {
            int sg = tid * 2 + i, row = sg >> 5, off = (sg & 31) << 3;
            cpa16(Vhs + buf*8448 + row*264 + off,
                  vh + (size_t)(t0 + row) * 65536 + dg * 256 + off);
            int jj = off >> 6, cc = off & 63;
            cpa16(Vvs + buf*8448 + row*264 + off,
                  vv + (size_t)(dg*4 + jj) * 65536 + (t0 + row) * 64 + cc);
        }
        cpcommit();
    };

    for (int dg = 0; dg < 8; dg++) {
        const int j0 = dg << 2;
        float a1[2][8][4];
        #pragma unroll
        for (int mt = 0; mt < 2; mt++)
            #pragma unroll
            for (int nt = 0; nt < 8; nt++)
                #pragma unroll
                for (int q = 0; q < 4; q++) a1[mt][nt][q] = 0.f;

        loadV(0, dg, 0);
        for (int c = 0; c < 8; c++) {
            if (c + 1 < 8) { loadV((c + 1) & 1, dg, c + 1); cpwait1(); }
            else cpwait0();
            __syncthreads();
            const int st = c & 1, t0 = c * 32;
            const __half* VH = Vhs + st * 8448;
            const __half* VV = Vvs + st * 8448;
            #pragma unroll
            for (int kk = 0; kk < 2; kk++) {
                uint32_t aH[2][4], aV[2][4];
                #pragma unroll
                for (int mt = 0; mt < 2; mt++) {
                    ldsm4(aH[mt], AHs + (wr*32 + mt*16 + (lane & 15)) * 264
                                      + t0 + kk*16 + ((lane >> 4) << 3));
                    ldsm4(aV[mt], AVs + (wr*32 + mt*16 + (lane & 15)) * 264
                                      + t0 + kk*16 + ((lane >> 4) << 3));
                }
                #pragma unroll
                for (int g = 0; g < 4; g++) {
                    int D0 = wc*64 + g*16;
                    int trow = kk*16 + ((lane >> 4) << 3) + (lane & 7);
                    int dcol = D0 + (((lane >> 3) & 1) << 3);
                    uint32_t r[4];
                    ldsm4t(r, VH + trow*264 + dcol);
                    #pragma unroll
                    for (int mt = 0; mt < 2; mt++) {
                        mma8(a1[mt][2*g],   aH[mt], r[0], r[2]);
                        mma8(a1[mt][2*g+1], aH[mt], r[1], r[3]);
                    }
                    ldsm4t(r, VV + trow*264 + dcol);
                    #pragma unroll
                    for (int mt = 0; mt < 2; mt++) {
                        mma8(a1[mt][2*g],   aV[mt], r[0], r[2]);
                        mma8(a1[mt][2*g+1], aV[mt], r[1], r[3]);
                    }
                }
            }
            __syncthreads();
        }

        #pragma unroll
        for (int mt = 0; mt < 2; mt++) {
            int r0 = wr*32 + mt*16 + (lane >> 2);
            #pragma unroll
            for (int nt = 0; nt < 8; nt++) {
                int col = wc*64 + nt*8 + 2*(lane & 3);
                *(__half2*)(XSs + r0*264 + col) =
                    __floats2half2_rn(a1[mt][nt][0], a1[mt][nt][1]);
                *(__half2*)(XSs + (r0+8)*264 + col) =
                    __floats2half2_rn(a1[mt][nt][2], a1[mt][nt][3]);
            }
        }
        __syncthreads();

        float a2[2][8][4];
        #pragma unroll
        for (int mt = 0; mt < 2; mt++)
            #pragma unroll
            for (int nt = 0; nt < 8; nt++)
                #pragma unroll
                for (int q = 0; q < 4; q++) a2[mt][nt][q] = 0.f;

        #pragma unroll
        for (int kk = 0; kk < 4; kk++) {
            uint32_t af[2][4];
            #pragma unroll
            for (int mt = 0; mt < 2; mt++)
                ldsm4(af[mt], XSs + (wr*32 + mt*16 + (lane & 15)) * 264
                                  + wc*64 + kk*16 + ((lane >> 4) << 3));
            #pragma unroll
            for (int g = 0; g < 4; g++) {
                uint32_t r[4];
                ldsm4(r, PWs + (g*16 + (lane & 15)) * 72
                             + kk*16 + ((lane >> 4) << 3));
                #pragma unroll
                for (int mt = 0; mt < 2; mt++) {
                    mma8(a2[mt][2*g],   af[mt], r[0], r[2]);
                    mma8(a2[mt][2*g+1], af[mt], r[1], r[3]);
                }
            }
        }

        #pragma unroll
        for (int mt = 0; mt < 2; mt++) {
            int r0 = wr*32 + mt*16 + (lane >> 2);
            #pragma unroll
            for (int nt = 0; nt < 8; nt++) {
                int co = nt*8 + 2*(lane & 3);
                float b0 = pbs[co], b1 = pbs[co + 1];
                float* o0 = out + ((size_t)(b*256 + s0 + r0) * 256
                                   + h*32 + j0 + wc) * 64 + co;
                float* o1 = out + ((size_t)(b*256 + s0 + r0 + 8) * 256
                                   + h*32 + j0 + wc) * 64 + co;
                *(float2*)o0 = make_float2(a2[mt][nt][0] + b0, a2[mt][nt][1] + b1);
                *(float2*)o1 = make_float2(a2[mt][nt][2] + b0, a2[mt][nt][3] + b1);
            }
        }
        __syncthreads();
    }
}

// ---------------------------------------------------------------------------
extern "C" void kernel_launch(void* const* d_in, const int* in_sizes, int n_in,
                              void* d_out, int out_size)
{
    const float* x      = (const float*)d_in[0];
    const float* qkv_w  = (const float*)d_in[1];
    const float* qkv_b  = (const float*)d_in[2];
    const float* proj_w = (const float*)d_in[3];
    const float* proj_b = (const float*)d_in[4];
    const float* t1     = (const float*)d_in[5];
    const float* t2     = (const float*)d_in[6];
    float* out = (float*)d_out;

    const int smem1 = 148608;   // ~145.1 KB
    const int smemF = 213248;   // ~208.3 KB

    cudaFuncSetAttribute((const void*)k_qkv,
                         cudaFuncAttributeMaxDynamicSharedMemorySize, smem1);
    cudaFuncSetAttribute((const void*)k_fused,
                         cudaFuncAttributeMaxDynamicSharedMemorySize, smemF);

    k_cvt  <<<64, 256>>>(qkv_w, proj_w);
    k_qkv  <<<dim3(512, 2),  512, smem1>>>(x, qkv_b);
    k_fused<<<dim3(64, 2),   512, smemF>>>(t1, t2, proj_b, out);
}